// round 4
// baseline (speedup 1.0000x reference)
#include <cuda_runtime.h>
#include <cstdint>

// ScaledDotProductAttention: out = softmax(mask_fill(QK^T*scale*W, M, -inf)) @ V
// B=8, NQ=SK=2048, D=128, fp32. Flash-style single pass, tf32 mma.sync.
// Mask arrives as int32 (harness converts jnp.bool_ -> int32).

namespace {

constexpr int BATCH = 8;
constexpr int NQ    = 2048;
constexpr int SKK   = 2048;
constexpr int DIM   = 128;
constexpr int BQ    = 64;   // q rows per CTA
constexpr int BK    = 64;   // k rows per tile
constexpr int NTHR  = 128;  // 4 warps, each owns 16 q rows
constexpr int QKSTR = 132;  // smem stride (words) for Q,K: 132 % 32 == 4 -> conflict-free frags
constexpr int VSTR  = 136;  // smem stride for V: 136 % 32 == 8 -> conflict-free frags
constexpr float SCALE = 0.088388347648318447f;  // 1/sqrt(128)
constexpr int SMEM_WORDS = BQ * QKSTR + BK * QKSTR + BK * VSTR;
constexpr int SMEM_BYTES = SMEM_WORDS * 4;  // 102400

__device__ __forceinline__ uint32_t f2tf(float x) {
    uint32_t u;
    asm("cvt.rna.tf32.f32 %0, %1;" : "=r"(u) : "f"(x));
    return u;
}

__device__ __forceinline__ void mma8(float (&d)[4], const uint32_t (&a)[4],
                                     const uint32_t (&b)[2]) {
    asm volatile(
        "mma.sync.aligned.m16n8k8.row.col.f32.tf32.tf32.f32 "
        "{%0,%1,%2,%3}, {%4,%5,%6,%7}, {%8,%9}, {%0,%1,%2,%3};\n"
        : "+f"(d[0]), "+f"(d[1]), "+f"(d[2]), "+f"(d[3])
        : "r"(a[0]), "r"(a[1]), "r"(a[2]), "r"(a[3]), "r"(b[0]), "r"(b[1]));
}

__global__ void __launch_bounds__(NTHR, 2)
attn_kernel(const float* __restrict__ Qg, const float* __restrict__ Kg,
            const float* __restrict__ Vg, const int* __restrict__ Mg,
            const float* __restrict__ Wg, float* __restrict__ Og) {
    extern __shared__ uint32_t smem[];
    uint32_t* Qs = smem;                 // [BQ][QKSTR] tf32 bits
    uint32_t* Ks = Qs + BQ * QKSTR;      // [BK][QKSTR] tf32 bits
    uint32_t* Vs = Ks + BK * QKSTR;      // [BK][VSTR]  tf32 bits

    const int b    = blockIdx.y;
    const int qt   = blockIdx.x;
    const int tid  = threadIdx.x;
    const int warp = tid >> 5;
    const int lane = tid & 31;
    const int g    = lane >> 2;   // row-within-16 group
    const int c    = lane & 3;    // col-within-quad
    const int r0   = warp * 16 + g;
    const int r1   = r0 + 8;

    // ---- load Q tile once (fp32 -> tf32 bits) ----
    {
        const float* src = Qg + ((size_t)b * NQ + (size_t)qt * BQ) * DIM;
        for (int i = tid; i < BQ * (DIM / 4); i += NTHR) {
            int row = i >> 5;            // DIM/4 = 32 float4 per row
            int cc  = (i & 31) * 4;
            float4 t = *(const float4*)(src + row * DIM + cc);
            uint32_t* qp = Qs + row * QKSTR + cc;
            uint4 u = make_uint4(f2tf(t.x), f2tf(t.y), f2tf(t.z), f2tf(t.w));
            *(uint4*)qp = u;
        }
    }

    // ---- accumulators ----
    float o[16][4];
#pragma unroll
    for (int i = 0; i < 16; i++) { o[i][0] = o[i][1] = o[i][2] = o[i][3] = 0.f; }
    float m0 = -1e30f, m1 = -1e30f;   // running row max (rows r0 / r1)
    float l0 = 0.f, l1 = 0.f;         // per-thread partial row sums

    const size_t row0g = (size_t)b * NQ + (size_t)qt * BQ + r0;
    const size_t row1g = (size_t)b * NQ + (size_t)qt * BQ + r1;
    const float* wr0 = Wg + row0g * SKK;
    const float* wr1 = Wg + row1g * SKK;
    const int*   mr0 = Mg + row0g * SKK;
    const int*   mr1 = Mg + row1g * SKK;

    for (int kt = 0; kt < SKK / BK; kt++) {
        __syncthreads();  // previous tile's smem reads (and iter-0 Q stores) done
        // ---- load K,V tiles (fp32 -> tf32 bits) ----
        {
            const float* ks = Kg + ((size_t)b * SKK + (size_t)kt * BK) * DIM;
            const float* vs = Vg + ((size_t)b * SKK + (size_t)kt * BK) * DIM;
            for (int i = tid; i < BK * (DIM / 4); i += NTHR) {
                int row = i >> 5;
                int cc  = (i & 31) * 4;
                float4 t = *(const float4*)(ks + row * DIM + cc);
                *(uint4*)(Ks + row * QKSTR + cc) =
                    make_uint4(f2tf(t.x), f2tf(t.y), f2tf(t.z), f2tf(t.w));
                float4 u = *(const float4*)(vs + row * DIM + cc);
                *(uint4*)(Vs + row * VSTR + cc) =
                    make_uint4(f2tf(u.x), f2tf(u.y), f2tf(u.z), f2tf(u.w));
            }
        }
        __syncthreads();

        // ---- S = Q @ K^T (64 x 64), warp handles rows [warp*16, warp*16+16) ----
        float s[8][4];
#pragma unroll
        for (int i = 0; i < 8; i++) s[i][0] = s[i][1] = s[i][2] = s[i][3] = 0.f;

#pragma unroll
        for (int k8 = 0; k8 < DIM / 8; k8++) {
            uint32_t a[4];
            a[0] = Qs[r0 * QKSTR + k8 * 8 + c];
            a[1] = Qs[r1 * QKSTR + k8 * 8 + c];
            a[2] = Qs[r0 * QKSTR + k8 * 8 + c + 4];
            a[3] = Qs[r1 * QKSTR + k8 * 8 + c + 4];
#pragma unroll
            for (int sn = 0; sn < 8; sn++) {
                uint32_t bb[2];
                bb[0] = Ks[(sn * 8 + g) * QKSTR + k8 * 8 + c];
                bb[1] = Ks[(sn * 8 + g) * QKSTR + k8 * 8 + c + 4];
                mma8(s[sn], a, bb);
            }
        }

        // ---- scale * weights, mask fill (int32 mask), track row max ----
        const float* w0p = wr0 + kt * BK;
        const float* w1p = wr1 + kt * BK;
        const int*   m0p = mr0 + kt * BK;
        const int*   m1p = mr1 + kt * BK;
        float mx0 = -1e30f, mx1 = -1e30f;
#pragma unroll
        for (int sn = 0; sn < 8; sn++) {
            int col = sn * 8 + 2 * c;
            float2 w0 = *(const float2*)(w0p + col);
            float2 w1 = *(const float2*)(w1p + col);
            int2 mm0 = *(const int2*)(m0p + col);
            int2 mm1 = *(const int2*)(m1p + col);
            s[sn][0] = mm0.x ? -1e30f : s[sn][0] * SCALE * w0.x;
            s[sn][1] = mm0.y ? -1e30f : s[sn][1] * SCALE * w0.y;
            s[sn][2] = mm1.x ? -1e30f : s[sn][2] * SCALE * w1.x;
            s[sn][3] = mm1.y ? -1e30f : s[sn][3] * SCALE * w1.y;
            mx0 = fmaxf(mx0, fmaxf(s[sn][0], s[sn][1]));
            mx1 = fmaxf(mx1, fmaxf(s[sn][2], s[sn][3]));
        }
        // quad reduce (lanes 4g..4g+3 hold one row)
        mx0 = fmaxf(mx0, __shfl_xor_sync(0xffffffffu, mx0, 1));
        mx0 = fmaxf(mx0, __shfl_xor_sync(0xffffffffu, mx0, 2));
        mx1 = fmaxf(mx1, __shfl_xor_sync(0xffffffffu, mx1, 1));
        mx1 = fmaxf(mx1, __shfl_xor_sync(0xffffffffu, mx1, 2));

        float mn0 = fmaxf(m0, mx0), mn1 = fmaxf(m1, mx1);
        float al0 = __expf(m0 - mn0), al1 = __expf(m1 - mn1);
        m0 = mn0; m1 = mn1;

        float ls0 = 0.f, ls1 = 0.f;
#pragma unroll
        for (int sn = 0; sn < 8; sn++) {
            s[sn][0] = __expf(s[sn][0] - mn0);
            s[sn][1] = __expf(s[sn][1] - mn0);
            s[sn][2] = __expf(s[sn][2] - mn1);
            s[sn][3] = __expf(s[sn][3] - mn1);
            ls0 += s[sn][0] + s[sn][1];
            ls1 += s[sn][2] + s[sn][3];
        }
        l0 = l0 * al0 + ls0;
        l1 = l1 * al1 + ls1;
#pragma unroll
        for (int i = 0; i < 16; i++) {
            o[i][0] *= al0; o[i][1] *= al0; o[i][2] *= al1; o[i][3] *= al1;
        }

        // ---- O += P @ V. Relayout P: C-frag cols {2c,2c+1} -> A-frag cols {c,c+4} ----
        const int lbase = lane & ~3;
        const int src1  = lbase + (c >> 1);
        const int src2  = src1 + 2;
#pragma unroll
        for (int kk = 0; kk < 8; kk++) {
            uint32_t p0 = f2tf(s[kk][0]), p1 = f2tf(s[kk][1]);
            uint32_t p2 = f2tf(s[kk][2]), p3 = f2tf(s[kk][3]);
            uint32_t e0 = __shfl_sync(0xffffffffu, p0, src1);
            uint32_t e1 = __shfl_sync(0xffffffffu, p1, src1);
            uint32_t e2 = __shfl_sync(0xffffffffu, p0, src2);
            uint32_t e3 = __shfl_sync(0xffffffffu, p1, src2);
            uint32_t f0 = __shfl_sync(0xffffffffu, p2, src1);
            uint32_t f1 = __shfl_sync(0xffffffffu, p3, src1);
            uint32_t f2 = __shfl_sync(0xffffffffu, p2, src2);
            uint32_t f3 = __shfl_sync(0xffffffffu, p3, src2);
            uint32_t a[4];
            if (c & 1) { a[0] = e1; a[2] = e3; a[1] = f1; a[3] = f3; }
            else       { a[0] = e0; a[2] = e2; a[1] = f0; a[3] = f2; }
#pragma unroll
            for (int sn = 0; sn < 16; sn++) {
                uint32_t bb[2];
                bb[0] = Vs[(kk * 8 + c) * VSTR + sn * 8 + g];
                bb[1] = Vs[(kk * 8 + c + 4) * VSTR + sn * 8 + g];
                mma8(o[sn], a, bb);
            }
        }
    }

    // ---- epilogue: finish row sums, normalize, store ----
    l0 += __shfl_xor_sync(0xffffffffu, l0, 1);
    l0 += __shfl_xor_sync(0xffffffffu, l0, 2);
    l1 += __shfl_xor_sync(0xffffffffu, l1, 1);
    l1 += __shfl_xor_sync(0xffffffffu, l1, 2);
    const float i0 = 1.f / l0, i1 = 1.f / l1;

    float* o0p = Og + row0g * DIM;
    float* o1p = Og + row1g * DIM;
#pragma unroll
    for (int sn = 0; sn < 16; sn++) {
        int dcol = sn * 8 + 2 * c;
        *(float2*)(o0p + dcol) = make_float2(o[sn][0] * i0, o[sn][1] * i0);
        *(float2*)(o1p + dcol) = make_float2(o[sn][2] * i1, o[sn][3] * i1);
    }
}

}  // namespace

extern "C" void kernel_launch(void* const* d_in, const int* in_sizes, int n_in,
                              void* d_out, int out_size) {
    (void)in_sizes; (void)n_in; (void)out_size;
    const float* q = (const float*)d_in[0];
    const float* k = (const float*)d_in[1];
    const float* v = (const float*)d_in[2];
    const int*   m = (const int*)d_in[3];    // bool mask -> int32 per harness dtype set
    const float* w = (const float*)d_in[4];
    float* out = (float*)d_out;

    cudaFuncSetAttribute(attn_kernel, cudaFuncAttributeMaxDynamicSharedMemorySize,
                         SMEM_BYTES);
    attn_kernel<<<dim3(NQ / BQ, BATCH), NTHR, SMEM_BYTES>>>(q, k, v, m, w, out);
}

// round 5
// speedup vs baseline: 1.1607x; 1.1607x over previous
#include <cuda_runtime.h>
#include <cstdint>

// ScaledDotProductAttention: out = softmax(mask_fill(QK^T*scale*W, M, -inf)) @ V
// B=8, NQ=SK=2048, D=128, fp32. Flash-style, tf32 mma.sync.
// R5: pre-converted tf32 K/V scratch + cp.async double-buffered tiles + hoisted W/M.

namespace {

constexpr int BATCH = 8;
constexpr int NQ    = 2048;
constexpr int SKK   = 2048;
constexpr int DIM   = 128;
constexpr int BQ    = 64;   // q rows per CTA
constexpr int BK    = 32;   // k rows per tile (double-buffered)
constexpr int NT    = SKK / BK;   // 64 tiles
constexpr int NTHR  = 128;  // 4 warps, each owns 16 q rows
constexpr int QKSTR = 132;  // smem stride (words) Q,K: %32==4 -> conflict-free frags
constexpr int VSTR  = 136;  // smem stride V: %32==8 -> conflict-free frags
constexpr float SCALE = 0.088388347648318447f;  // 1/sqrt(128)

constexpr int QWORDS = BQ * QKSTR;          // 8448
constexpr int KWORDS = BK * QKSTR;          // 4224
constexpr int VWORDS = BK * VSTR;           // 4352
constexpr int OFF_K0 = QWORDS;
constexpr int OFF_K1 = QWORDS + KWORDS;
constexpr int OFF_V0 = QWORDS + 2 * KWORDS;
constexpr int OFF_V1 = OFF_V0 + VWORDS;
constexpr int SMEM_WORDS = QWORDS + 2 * KWORDS + 2 * VWORDS;  // 25600
constexpr int SMEM_BYTES = SMEM_WORDS * 4;                    // 102400

// tf32-converted K/V scratch (8.4 MB each)
__device__ uint4 Ktf[BATCH * SKK * DIM / 4];
__device__ uint4 Vtf[BATCH * SKK * DIM / 4];

__device__ __forceinline__ uint32_t f2tf(float x) {
    uint32_t u;
    asm("cvt.rna.tf32.f32 %0, %1;" : "=r"(u) : "f"(x));
    return u;
}

__device__ __forceinline__ void mma8(float (&d)[4], const uint32_t (&a)[4],
                                     const uint32_t (&b)[2]) {
    asm volatile(
        "mma.sync.aligned.m16n8k8.row.col.f32.tf32.tf32.f32 "
        "{%0,%1,%2,%3}, {%4,%5,%6,%7}, {%8,%9}, {%0,%1,%2,%3};\n"
        : "+f"(d[0]), "+f"(d[1]), "+f"(d[2]), "+f"(d[3])
        : "r"(a[0]), "r"(a[1]), "r"(a[2]), "r"(a[3]), "r"(b[0]), "r"(b[1]));
}

__device__ __forceinline__ void cp16(uint32_t dst, const void* src) {
    asm volatile("cp.async.cg.shared.global [%0], [%1], 16;" :: "r"(dst), "l"(src));
}

// ---- pre-pass: fp32 -> tf32 for K and V ----
__global__ void cvt_kernel(const float4* __restrict__ K, const float4* __restrict__ V) {
    int i = blockIdx.x * 256 + threadIdx.x;
    float4 a = K[i];
    Ktf[i] = make_uint4(f2tf(a.x), f2tf(a.y), f2tf(a.z), f2tf(a.w));
    float4 b = V[i];
    Vtf[i] = make_uint4(f2tf(b.x), f2tf(b.y), f2tf(b.z), f2tf(b.w));
}

__global__ void __launch_bounds__(NTHR, 2)
attn_kernel(const float* __restrict__ Qg, const int* __restrict__ Mg,
            const float* __restrict__ Wg, float* __restrict__ Og) {
    extern __shared__ uint32_t smem[];
    uint32_t* Qs = smem;  // [BQ][QKSTR] tf32 bits
    const uint32_t smem_u32 = (uint32_t)__cvta_generic_to_shared(smem);

    const int b    = blockIdx.y;
    const int qt   = blockIdx.x;
    const int tid  = threadIdx.x;
    const int warp = tid >> 5;
    const int lane = tid & 31;
    const int g    = lane >> 2;
    const int c    = lane & 3;
    const int r0   = warp * 16 + g;
    const int r1   = r0 + 8;

    // per-thread cp.async coordinates (8 chunks of 16B per array per tile)
    const int cr = tid >> 5;        // base row 0..3 (+4 per step, 8 steps = 32 rows)
    const int c4 = lane;            // 16B-chunk within row, 0..31

    const uint4* ktile0 = Ktf + ((size_t)b * SKK) * (DIM / 16) * 4;
    const uint4* vtile0 = Vtf + ((size_t)b * SKK) * (DIM / 16) * 4;

    // ---- prologue: issue tile 0, and load Q (fp32 -> tf32) ----
    {
        const uint4* ks = (const uint4*)Ktf + ((size_t)b * SKK + 0) * (DIM / 4);
        const uint4* vs = (const uint4*)Vtf + ((size_t)b * SKK + 0) * (DIM / 4);
#pragma unroll
        for (int j = 0; j < 8; j++) {
            int row = cr + j * 4;
            cp16(smem_u32 + (OFF_K0 + row * QKSTR + c4 * 4) * 4, ks + row * 32 + c4);
            cp16(smem_u32 + (OFF_V0 + row * VSTR + c4 * 4) * 4, vs + row * 32 + c4);
        }
        asm volatile("cp.async.commit_group;");

        const float* src = Qg + ((size_t)b * NQ + (size_t)qt * BQ) * DIM;
#pragma unroll 4
        for (int i = tid; i < BQ * (DIM / 4); i += NTHR) {
            int row = i >> 5;
            int cc  = (i & 31) * 4;
            float4 t = *(const float4*)(src + row * DIM + cc);
            *(uint4*)(Qs + row * QKSTR + cc) =
                make_uint4(f2tf(t.x), f2tf(t.y), f2tf(t.z), f2tf(t.w));
        }
    }

    // ---- accumulators ----
    float o[16][4];
#pragma unroll
    for (int i = 0; i < 16; i++) { o[i][0] = o[i][1] = o[i][2] = o[i][3] = 0.f; }
    float m0 = -1e30f, m1 = -1e30f;
    float l0 = 0.f, l1 = 0.f;

    const size_t row0g = (size_t)b * NQ + (size_t)qt * BQ + r0;
    const size_t row1g = (size_t)b * NQ + (size_t)qt * BQ + r1;
    const float* wr0 = Wg + row0g * SKK;
    const float* wr1 = Wg + row1g * SKK;
    const int*   mr0 = Mg + row0g * SKK;
    const int*   mr1 = Mg + row1g * SKK;

    for (int kt = 0; kt < NT; kt++) {
        // issue next tile into the other buffer
        if (kt + 1 < NT) {
            const int nbuf = (kt + 1) & 1;
            const uint4* ks = (const uint4*)Ktf + ((size_t)b * SKK + (kt + 1) * BK) * (DIM / 4);
            const uint4* vs = (const uint4*)Vtf + ((size_t)b * SKK + (kt + 1) * BK) * (DIM / 4);
            const int koff = nbuf ? OFF_K1 : OFF_K0;
            const int voff = nbuf ? OFF_V1 : OFF_V0;
#pragma unroll
            for (int j = 0; j < 8; j++) {
                int row = cr + j * 4;
                cp16(smem_u32 + (koff + row * QKSTR + c4 * 4) * 4, ks + row * 32 + c4);
                cp16(smem_u32 + (voff + row * VSTR + c4 * 4) * 4, vs + row * 32 + c4);
            }
            asm volatile("cp.async.commit_group;");
            asm volatile("cp.async.wait_group 1;");
        } else {
            asm volatile("cp.async.wait_group 0;");
        }
        __syncthreads();  // tile kt visible to all (also fences Q stores on kt==0)

        const uint32_t* Ks = smem + ((kt & 1) ? OFF_K1 : OFF_K0);
        const uint32_t* Vs = smem + ((kt & 1) ? OFF_V1 : OFF_V0);

        // ---- hoist W / mask loads for this tile (cols sn*8+2c, rows r0/r1) ----
        const float* w0p = wr0 + kt * BK;
        const float* w1p = wr1 + kt * BK;
        const int*   m0p = mr0 + kt * BK;
        const int*   m1p = mr1 + kt * BK;
        float2 w0v[4], w1v[4];
        int2   mm0v[4], mm1v[4];
#pragma unroll
        for (int sn = 0; sn < 4; sn++) {
            int col = sn * 8 + 2 * c;
            w0v[sn]  = *(const float2*)(w0p + col);
            w1v[sn]  = *(const float2*)(w1p + col);
            mm0v[sn] = *(const int2*)(m0p + col);
            mm1v[sn] = *(const int2*)(m1p + col);
        }

        // ---- S = Q @ K^T (64 x 32) ----
        float s[4][4];
#pragma unroll
        for (int i = 0; i < 4; i++) s[i][0] = s[i][1] = s[i][2] = s[i][3] = 0.f;

#pragma unroll
        for (int k8 = 0; k8 < DIM / 8; k8++) {
            uint32_t a[4];
            a[0] = Qs[r0 * QKSTR + k8 * 8 + c];
            a[1] = Qs[r1 * QKSTR + k8 * 8 + c];
            a[2] = Qs[r0 * QKSTR + k8 * 8 + c + 4];
            a[3] = Qs[r1 * QKSTR + k8 * 8 + c + 4];
#pragma unroll
            for (int sn = 0; sn < 4; sn++) {
                uint32_t bb[2];
                bb[0] = Ks[(sn * 8 + g) * QKSTR + k8 * 8 + c];
                bb[1] = Ks[(sn * 8 + g) * QKSTR + k8 * 8 + c + 4];
                mma8(s[sn], a, bb);
            }
        }

        // ---- scale * weights, mask fill, row max ----
        float mx0 = -1e30f, mx1 = -1e30f;
#pragma unroll
        for (int sn = 0; sn < 4; sn++) {
            s[sn][0] = mm0v[sn].x ? -1e30f : s[sn][0] * SCALE * w0v[sn].x;
            s[sn][1] = mm0v[sn].y ? -1e30f : s[sn][1] * SCALE * w0v[sn].y;
            s[sn][2] = mm1v[sn].x ? -1e30f : s[sn][2] * SCALE * w1v[sn].x;
            s[sn][3] = mm1v[sn].y ? -1e30f : s[sn][3] * SCALE * w1v[sn].y;
            mx0 = fmaxf(mx0, fmaxf(s[sn][0], s[sn][1]));
            mx1 = fmaxf(mx1, fmaxf(s[sn][2], s[sn][3]));
        }
        mx0 = fmaxf(mx0, __shfl_xor_sync(0xffffffffu, mx0, 1));
        mx0 = fmaxf(mx0, __shfl_xor_sync(0xffffffffu, mx0, 2));
        mx1 = fmaxf(mx1, __shfl_xor_sync(0xffffffffu, mx1, 1));
        mx1 = fmaxf(mx1, __shfl_xor_sync(0xffffffffu, mx1, 2));

        float mn0 = fmaxf(m0, mx0), mn1 = fmaxf(m1, mx1);
        float al0 = __expf(m0 - mn0), al1 = __expf(m1 - mn1);
        m0 = mn0; m1 = mn1;

        float ls0 = 0.f, ls1 = 0.f;
#pragma unroll
        for (int sn = 0; sn < 4; sn++) {
            s[sn][0] = __expf(s[sn][0] - mn0);
            s[sn][1] = __expf(s[sn][1] - mn0);
            s[sn][2] = __expf(s[sn][2] - mn1);
            s[sn][3] = __expf(s[sn][3] - mn1);
            ls0 += s[sn][0] + s[sn][1];
            ls1 += s[sn][2] + s[sn][3];
        }
        l0 = l0 * al0 + ls0;
        l1 = l1 * al1 + ls1;
#pragma unroll
        for (int i = 0; i < 16; i++) {
            o[i][0] *= al0; o[i][1] *= al0; o[i][2] *= al1; o[i][3] *= al1;
        }

        // ---- O += P @ V. Relayout P: C-frag cols {2c,2c+1} -> A-frag cols {c,c+4} ----
        const int lbase = lane & ~3;
        const int src1  = lbase + (c >> 1);
        const int src2  = src1 + 2;
#pragma unroll
        for (int kk = 0; kk < 4; kk++) {
            uint32_t p0 = f2tf(s[kk][0]), p1 = f2tf(s[kk][1]);
            uint32_t p2 = f2tf(s[kk][2]), p3 = f2tf(s[kk][3]);
            uint32_t e0 = __shfl_sync(0xffffffffu, p0, src1);
            uint32_t e1 = __shfl_sync(0xffffffffu, p1, src1);
            uint32_t e2 = __shfl_sync(0xffffffffu, p0, src2);
            uint32_t e3 = __shfl_sync(0xffffffffu, p1, src2);
            uint32_t f0 = __shfl_sync(0xffffffffu, p2, src1);
            uint32_t f1 = __shfl_sync(0xffffffffu, p3, src1);
            uint32_t f2 = __shfl_sync(0xffffffffu, p2, src2);
            uint32_t f3 = __shfl_sync(0xffffffffu, p3, src2);
            uint32_t a[4];
            if (c & 1) { a[0] = e1; a[2] = e3; a[1] = f1; a[3] = f3; }
            else       { a[0] = e0; a[2] = e2; a[1] = f0; a[3] = f2; }
#pragma unroll
            for (int sn = 0; sn < 16; sn++) {
                uint32_t bb[2];
                bb[0] = Vs[(kk * 8 + c) * VSTR + sn * 8 + g];
                bb[1] = Vs[(kk * 8 + c + 4) * VSTR + sn * 8 + g];
                mma8(o[sn], a, bb);
            }
        }
        __syncthreads();  // done reading buf before it is re-filled
    }

    // ---- epilogue ----
    l0 += __shfl_xor_sync(0xffffffffu, l0, 1);
    l0 += __shfl_xor_sync(0xffffffffu, l0, 2);
    l1 += __shfl_xor_sync(0xffffffffu, l1, 1);
    l1 += __shfl_xor_sync(0xffffffffu, l1, 2);
    const float i0 = 1.f / l0, i1 = 1.f / l1;

    float* o0p = Og + row0g * DIM;
    float* o1p = Og + row1g * DIM;
#pragma unroll
    for (int sn = 0; sn < 16; sn++) {
        int dcol = sn * 8 + 2 * c;
        *(float2*)(o0p + dcol) = make_float2(o[sn][0] * i0, o[sn][1] * i0);
        *(float2*)(o1p + dcol) = make_float2(o[sn][2] * i1, o[sn][3] * i1);
    }
}

}  // namespace

extern "C" void kernel_launch(void* const* d_in, const int* in_sizes, int n_in,
                              void* d_out, int out_size) {
    (void)in_sizes; (void)n_in; (void)out_size;
    const float* q = (const float*)d_in[0];
    const float* k = (const float*)d_in[1];
    const float* v = (const float*)d_in[2];
    const int*   m = (const int*)d_in[3];
    const float* w = (const float*)d_in[4];
    float* out = (float*)d_out;

    // pre-pass: K,V fp32 -> tf32 scratch
    cvt_kernel<<<BATCH * SKK * DIM / 4 / 256, 256>>>((const float4*)k, (const float4*)v);

    cudaFuncSetAttribute(attn_kernel, cudaFuncAttributeMaxDynamicSharedMemorySize,
                         SMEM_BYTES);
    attn_kernel<<<dim3(NQ / BQ, BATCH), NTHR, SMEM_BYTES>>>(q, m, w, out);
}

// round 7
// speedup vs baseline: 1.2442x; 1.0719x over previous
#include <cuda_runtime.h>
#include <cstdint>

// ScaledDotProductAttention: out = softmax(mask_fill(QK^T*scale*W, M, -inf)) @ V
// B=8, NQ=SK=2048, D=128, fp32. Flash-style, tf32 mma.sync.
// R6: ldmatrix.x4 operand loads, transposed-V scratch, split S chains,
//     cp.async double-buffered K/V tiles.

namespace {

constexpr int BATCH = 8;
constexpr int NQ    = 2048;
constexpr int SKK   = 2048;
constexpr int DIM   = 128;
constexpr int BQ    = 64;   // q rows per CTA
constexpr int BK    = 32;   // k rows per tile (double-buffered)
constexpr int NT    = SKK / BK;   // 64 tiles
constexpr int NTHR  = 128;  // 4 warps, each owns 16 q rows
constexpr int QKSTR = 132;  // smem word stride Q,K rows: %32==4 -> LDSM conflict-free
constexpr int VTSTR = 36;   // smem word stride Vt rows: %32==4 -> LDSM conflict-free
constexpr float SCALE = 0.088388347648318447f;  // 1/sqrt(128)

constexpr int QWORDS  = BQ * QKSTR;   // 8448
constexpr int KWORDS  = BK * QKSTR;   // 4224
constexpr int VTWORDS = DIM * VTSTR;  // 4608 (128 d-rows x 36)
constexpr int OFF_K0 = QWORDS;                 // 8448
constexpr int OFF_K1 = OFF_K0 + KWORDS;        // 12672
constexpr int OFF_V0 = OFF_K1 + KWORDS;        // 16896
constexpr int OFF_V1 = OFF_V0 + VTWORDS;       // 21504
constexpr int SMEM_WORDS = OFF_V1 + VTWORDS;   // 26112
constexpr int SMEM_BYTES = SMEM_WORDS * 4;     // 104448

// tf32-converted scratch: K [b][k][d], V transposed [b][d][k]
__device__ uint32_t Ktf[BATCH * SKK * DIM];
__device__ uint32_t Vtf[BATCH * DIM * SKK];

__device__ __forceinline__ uint32_t f2tf(float x) {
    uint32_t u;
    asm("cvt.rna.tf32.f32 %0, %1;" : "=r"(u) : "f"(x));
    return u;
}

__device__ __forceinline__ void mma8(float (&d)[4], const uint32_t (&a)[4],
                                     uint32_t b0, uint32_t b1) {
    asm volatile(
        "mma.sync.aligned.m16n8k8.row.col.f32.tf32.tf32.f32 "
        "{%0,%1,%2,%3}, {%4,%5,%6,%7}, {%8,%9}, {%0,%1,%2,%3};\n"
        : "+f"(d[0]), "+f"(d[1]), "+f"(d[2]), "+f"(d[3])
        : "r"(a[0]), "r"(a[1]), "r"(a[2]), "r"(a[3]), "r"(b0), "r"(b1));
}

__device__ __forceinline__ void ldsm4(uint32_t (&r)[4], uint32_t addr) {
    asm volatile("ldmatrix.sync.aligned.m8n8.x4.shared.b16 {%0,%1,%2,%3}, [%4];"
                 : "=r"(r[0]), "=r"(r[1]), "=r"(r[2]), "=r"(r[3]) : "r"(addr));
}

__device__ __forceinline__ void cp16(uint32_t dst, const void* src) {
    asm volatile("cp.async.cg.shared.global [%0], [%1], 16;" :: "r"(dst), "l"(src));
}

// ---- pre-pass: K fp32 -> tf32 (elementwise) ----
__global__ void cvtK_kernel(const float4* __restrict__ K) {
    int i = blockIdx.x * 256 + threadIdx.x;
    float4 a = K[i];
    ((uint4*)Ktf)[i] = make_uint4(f2tf(a.x), f2tf(a.y), f2tf(a.z), f2tf(a.w));
}

// ---- pre-pass: V fp32 [b][k][d] -> tf32 transposed [b][d][k] ----
__global__ void cvtV_kernel(const float* __restrict__ V) {
    __shared__ uint32_t t[32][33];
    int b = blockIdx.z, k0 = blockIdx.x * 32, d0 = blockIdx.y * 32;
    const float* src = V + ((size_t)b * SKK + k0) * DIM + d0;
    int tx = threadIdx.x, ty = threadIdx.y;
#pragma unroll
    for (int i = ty; i < 32; i += 8)
        t[tx][i] = f2tf(src[(size_t)i * DIM + tx]);   // t[d][k]
    __syncthreads();
    uint32_t* dst = Vtf + ((size_t)b * DIM + d0) * SKK + k0;
#pragma unroll
    for (int i = ty; i < 32; i += 8)
        dst[(size_t)i * SKK + tx] = t[i][tx];
}

// ---- tile loader: K (row-major) + Vt (d-major) via cp.async ----
__device__ __forceinline__ void load_tile(uint32_t smem_u32, int koff, int voff,
                                          int b, int kt, int tid) {
    const uint4* ks = (const uint4*)Ktf + ((size_t)b * SKK + (size_t)kt * BK) * (DIM / 4);
#pragma unroll
    for (int j = 0; j < 8; j++) {
        int cidx = j * NTHR + tid;
        int row = cidx >> 5, col = cidx & 31;   // 32 rows x 32 chunks
        cp16(smem_u32 + (uint32_t)(koff + row * QKSTR + col * 4) * 4,
             ks + row * 32 + col);
    }
    const uint32_t* vbase = Vtf + (size_t)b * DIM * SKK + (size_t)kt * BK;
#pragma unroll
    for (int j = 0; j < 8; j++) {
        int cidx = j * NTHR + tid;
        int row = cidx >> 3, col = cidx & 7;    // 128 d-rows x 8 chunks
        cp16(smem_u32 + (uint32_t)(voff + row * VTSTR + col * 4) * 4,
             (const uint4*)(vbase + (size_t)row * SKK) + col);
    }
    asm volatile("cp.async.commit_group;");
}

__global__ void __launch_bounds__(NTHR, 2)
attn_kernel(const float* __restrict__ Qg, const int* __restrict__ Mg,
            const float* __restrict__ Wg, float* __restrict__ Og) {
    extern __shared__ uint32_t smem[];
    uint32_t* Qs = smem;  // [BQ][QKSTR] tf32 bits
    const uint32_t smem_u32 = (uint32_t)__cvta_generic_to_shared(smem);

    const int b    = blockIdx.y;
    const int qt   = blockIdx.x;
    const int tid  = threadIdx.x;
    const int warp = tid >> 5;
    const int lane = tid & 31;
    const int g    = lane >> 2;
    const int c    = lane & 3;
    const int r0   = warp * 16 + g;
    const int r1   = r0 + 8;

    // ---- per-lane LDSM base offsets (word units) ----
    // A (Q): matrices {rows 0-7, 8-15} x {col+0, col+4} of the warp's 16 rows
    const uint32_t q_ld = (uint32_t)((warp * 16 + (lane & 15)) * QKSTR + ((lane >> 4) << 2));
    // B (K / Vt): matrices {snA rows, snA+1 rows} x {col+0, col+4}
    const uint32_t b_row = (uint32_t)(((lane >> 4) & 1) * 8 + (lane & 7));
    const uint32_t b_col = (uint32_t)(((lane >> 3) & 1) << 2);
    const uint32_t k_ld = b_row * QKSTR + b_col;
    const uint32_t v_ld = b_row * VTSTR + b_col;

    // ---- prologue: issue tile 0, load Q (fp32 -> tf32) ----
    load_tile(smem_u32, OFF_K0, OFF_V0, b, 0, tid);
    {
        const float* src = Qg + ((size_t)b * NQ + (size_t)qt * BQ) * DIM;
#pragma unroll 4
        for (int i = tid; i < BQ * (DIM / 4); i += NTHR) {
            int row = i >> 5;
            int cc  = (i & 31) * 4;
            float4 t = *(const float4*)(src + row * DIM + cc);
            *(uint4*)(Qs + row * QKSTR + cc) =
                make_uint4(f2tf(t.x), f2tf(t.y), f2tf(t.z), f2tf(t.w));
        }
    }

    // ---- accumulators ----
    float o[16][4];
#pragma unroll
    for (int i = 0; i < 16; i++) { o[i][0] = o[i][1] = o[i][2] = o[i][3] = 0.f; }
    float m0 = -1e30f, m1 = -1e30f;
    float l0 = 0.f, l1 = 0.f;

    const size_t row0g = (size_t)b * NQ + (size_t)qt * BQ + r0;
    const size_t row1g = (size_t)b * NQ + (size_t)qt * BQ + r1;
    const float* wr0 = Wg + row0g * SKK;
    const float* wr1 = Wg + row1g * SKK;
    const int*   mr0 = Mg + row0g * SKK;
    const int*   mr1 = Mg + row1g * SKK;

    for (int kt = 0; kt < NT; kt++) {
        if (kt + 1 < NT) {
            const int nbuf = (kt + 1) & 1;
            load_tile(smem_u32, nbuf ? OFF_K1 : OFF_K0, nbuf ? OFF_V1 : OFF_V0,
                      b, kt + 1, tid);
            asm volatile("cp.async.wait_group 1;");
        } else {
            asm volatile("cp.async.wait_group 0;");
        }
        __syncthreads();  // tile kt visible (also fences Q stores on kt==0)

        const uint32_t kbase = smem_u32 + (uint32_t)((kt & 1) ? OFF_K1 : OFF_K0) * 4;
        const uint32_t vbase = smem_u32 + (uint32_t)((kt & 1) ? OFF_V1 : OFF_V0) * 4;
        const uint32_t qaddr  = smem_u32 + q_ld * 4;
        const uint32_t kaddr0 = kbase + k_ld * 4;                       // sn 0,1
        const uint32_t kaddr1 = kbase + (16 * QKSTR + k_ld) * 4;        // sn 2,3

        // ---- hoisted W / mask loads (cols sn*8+2c, rows r0/r1) ----
        const float* w0p = wr0 + kt * BK;
        const float* w1p = wr1 + kt * BK;
        const int*   m0p = mr0 + kt * BK;
        const int*   m1p = mr1 + kt * BK;
        float2 w0v[4], w1v[4];
        int2   mm0v[4], mm1v[4];
#pragma unroll
        for (int sn = 0; sn < 4; sn++) {
            int col = sn * 8 + 2 * c;
            w0v[sn]  = *(const float2*)(w0p + col);
            w1v[sn]  = *(const float2*)(w1p + col);
            mm0v[sn] = *(const int2*)(m0p + col);
            mm1v[sn] = *(const int2*)(m1p + col);
        }

        // ---- S = Q @ K^T (64 x 32), split even/odd-k8 chains ----
        float sa[4][4], sb[4][4];
#pragma unroll
        for (int i = 0; i < 4; i++) {
            sa[i][0] = sa[i][1] = sa[i][2] = sa[i][3] = 0.f;
            sb[i][0] = sb[i][1] = sb[i][2] = sb[i][3] = 0.f;
        }
#pragma unroll
        for (int k8 = 0; k8 < DIM / 8; k8++) {
            uint32_t a[4], kb0[4], kb1[4];
            ldsm4(a,   qaddr  + k8 * 32);
            ldsm4(kb0, kaddr0 + k8 * 32);
            ldsm4(kb1, kaddr1 + k8 * 32);
            if (k8 & 1) {
                mma8(sb[0], a, kb0[0], kb0[1]);
                mma8(sb[1], a, kb0[2], kb0[3]);
                mma8(sb[2], a, kb1[0], kb1[1]);
                mma8(sb[3], a, kb1[2], kb1[3]);
            } else {
                mma8(sa[0], a, kb0[0], kb0[1]);
                mma8(sa[1], a, kb0[2], kb0[3]);
                mma8(sa[2], a, kb1[0], kb1[1]);
                mma8(sa[3], a, kb1[2], kb1[3]);
            }
        }
        float s[4][4];
#pragma unroll
        for (int i = 0; i < 4; i++) {
            s[i][0] = sa[i][0] + sb[i][0];
            s[i][1] = sa[i][1] + sb[i][1];
            s[i][2] = sa[i][2] + sb[i][2];
            s[i][3] = sa[i][3] + sb[i][3];
        }

        // ---- scale * weights, mask fill, row max ----
        float mx0 = -1e30f, mx1 = -1e30f;
#pragma unroll
        for (int sn = 0; sn < 4; sn++) {
            s[sn][0] = mm0v[sn].x ? -1e30f : s[sn][0] * SCALE * w0v[sn].x;
            s[sn][1] = mm0v[sn].y ? -1e30f : s[sn][1] * SCALE * w0v[sn].y;
            s[sn][2] = mm1v[sn].x ? -1e30f : s[sn][2] * SCALE * w1v[sn].x;
            s[sn][3] = mm1v[sn].y ? -1e30f : s[sn][3] * SCALE * w1v[sn].y;
            mx0 = fmaxf(mx0, fmaxf(s[sn][0], s[sn][1]));
            mx1 = fmaxf(mx1, fmaxf(s[sn][2], s[sn][3]));
        }
        mx0 = fmaxf(mx0, __shfl_xor_sync(0xffffffffu, mx0, 1));
        mx0 = fmaxf(mx0, __shfl_xor_sync(0xffffffffu, mx0, 2));
        mx1 = fmaxf(mx1, __shfl_xor_sync(0xffffffffu, mx1, 1));
        mx1 = fmaxf(mx1, __shfl_xor_sync(0xffffffffu, mx1, 2));

        float mn0 = fmaxf(m0, mx0), mn1 = fmaxf(m1, mx1);
        float al0 = __expf(m0 - mn0), al1 = __expf(m1 - mn1);
        m0 = mn0; m1 = mn1;

        float ls0 = 0.f, ls1 = 0.f;
#pragma unroll
        for (int sn = 0; sn < 4; sn++) {
            s[sn][0] = __expf(s[sn][0] - mn0);
            s[sn][1] = __expf(s[sn][1] - mn0);
            s[sn][2] = __expf(s[sn][2] - mn1);
            s[sn][3] = __expf(s[sn][3] - mn1);
            ls0 += s[sn][0] + s[sn][1];
            ls1 += s[sn][2] + s[sn][3];
        }
        l0 = l0 * al0 + ls0;
        l1 = l1 * al1 + ls1;
#pragma unroll
        for (int i = 0; i < 16; i++) {
            o[i][0] *= al0; o[i][1] *= al0; o[i][2] *= al1; o[i][3] *= al1;
        }

        // ---- O += P @ V. Relayout P: C-frag cols {2c,2c+1} -> A-frag cols {c,c+4} ----
        const int lbase = lane & ~3;
        const int src1  = lbase + (c >> 1);
        const int src2  = src1 + 2;
#pragma unroll
        for (int kk = 0; kk < 4; kk++) {
            uint32_t p0 = f2tf(s[kk][0]), p1 = f2tf(s[kk][1]);
            uint32_t p2 = f2tf(s[kk][2]), p3 = f2tf(s[kk][3]);
            uint32_t e0 = __shfl_sync(0xffffffffu, p0, src1);
            uint32_t e1 = __shfl_sync(0xffffffffu, p1, src1);
            uint32_t e2 = __shfl_sync(0xffffffffu, p0, src2);
            uint32_t e3 = __shfl_sync(0xffffffffu, p1, src2);
            uint32_t f0 = __shfl_sync(0xffffffffu, p2, src1);
            uint32_t f1 = __shfl_sync(0xffffffffu, p3, src1);
            uint32_t f2 = __shfl_sync(0xffffffffu, p2, src2);
            uint32_t f3 = __shfl_sync(0xffffffffu, p3, src2);
            uint32_t a[4];
            if (c & 1) { a[0] = e1; a[2] = e3; a[1] = f1; a[3] = f3; }
            else       { a[0] = e0; a[2] = e2; a[1] = f0; a[3] = f2; }
            const uint32_t vcol = vbase + (v_ld + kk * 8) * 4;
#pragma unroll
            for (int j = 0; j < 8; j++) {
                uint32_t vb[4];
                ldsm4(vb, vcol + (uint32_t)(j * 16 * VTSTR) * 4);  // d-rows 16j..16j+15
                mma8(o[2 * j],     a, vb[0], vb[1]);
                mma8(o[2 * j + 1], a, vb[2], vb[3]);
            }
        }
        __syncthreads();  // done reading buf before it is re-filled
    }

    // ---- epilogue ----
    l0 += __shfl_xor_sync(0xffffffffu, l0, 1);
    l0 += __shfl_xor_sync(0xffffffffu, l0, 2);
    l1 += __shfl_xor_sync(0xffffffffu, l1, 1);
    l1 += __shfl_xor_sync(0xffffffffu, l1, 2);
    const float i0 = 1.f / l0, i1 = 1.f / l1;

    float* o0p = Og + row0g * DIM;
    float* o1p = Og + row1g * DIM;
#pragma unroll
    for (int sn = 0; sn < 16; sn++) {
        int dcol = sn * 8 + 2 * c;
        *(float2*)(o0p + dcol) = make_float2(o[sn][0] * i0, o[sn][1] * i0);
        *(float2*)(o1p + dcol) = make_float2(o[sn][2] * i1, o[sn][3] * i1);
    }
}

}  // namespace

extern "C" void kernel_launch(void* const* d_in, const int* in_sizes, int n_in,
                              void* d_out, int out_size) {
    (void)in_sizes; (void)n_in; (void)out_size;
    const float* q = (const float*)d_in[0];
    const float* k = (const float*)d_in[1];
    const float* v = (const float*)d_in[2];
    const int*   m = (const int*)d_in[3];
    const float* w = (const float*)d_in[4];
    float* out = (float*)d_out;

    cvtK_kernel<<<BATCH * SKK * DIM / 4 / 256, 256>>>((const float4*)k);
    cvtV_kernel<<<dim3(SKK / 32, DIM / 32, BATCH), dim3(32, 8)>>>(v);

    cudaFuncSetAttribute(attn_kernel, cudaFuncAttributeMaxDynamicSharedMemorySize,
                         SMEM_BYTES);
    attn_kernel<<<dim3(NQ / BQ, BATCH), NTHR, SMEM_BYTES>>>(q, m, w, out);
}